// round 6
// baseline (speedup 1.0000x reference)
#include <cuda_runtime.h>

#define NN    64          // nodes per graph
#define HID   32
#define NE    1024        // edges per graph
#define NF    3
#define NROWS (NE + NF)   // 1027
#define T     512
#define MT    36          // padded transposed-M row stride
#define PADE  1216        // max padded CSR length (1024 + 64*3)

typedef unsigned long long u64;

__device__ __forceinline__ u64 pk2(float x, float y) {
    u64 r; asm("mov.b64 %0,{%1,%2};" : "=l"(r) : "f"(x), "f"(y)); return r;
}
__device__ __forceinline__ u64 dup2(float x) { return pk2(x, x); }
__device__ __forceinline__ float2 up2(u64 a) {
    float2 r; asm("mov.b64 {%0,%1},%2;" : "=f"(r.x), "=f"(r.y) : "l"(a)); return r;
}
__device__ __forceinline__ u64 f2fma(u64 a, u64 b, u64 c) {
    u64 r; asm("fma.rn.f32x2 %0,%1,%2,%3;" : "=l"(r) : "l"(a), "l"(b), "l"(c)); return r;
}
__device__ __forceinline__ u64 f2add(u64 a, u64 b) {
    u64 r; asm("add.rn.f32x2 %0,%1,%2;" : "=l"(r) : "l"(a), "l"(b)); return r;
}
__device__ __forceinline__ u64 relu2(u64 a) {
    float2 f = up2(a); return pk2(fmaxf(f.x, 0.f), fmaxf(f.y, 0.f));
}
__device__ __forceinline__ u64 dll(double d) { return __double_as_longlong(d); }

// batch-invariant scratch
__device__ int   g_off[NN + 1];     // PADDED csr offsets (multiples of 4 per seg)
__device__ int   g_deg[NN];         // true degrees
__device__ int   g_rank[NE];        // padded CSR slot of original edge e
__device__ float g_M1t[HID * MT];   // (W2 @ Wl[4:36])^T, padded stride 36
__device__ float g_M2t[HID * MT];   // (W2 @ Wl[40:72])^T
__device__ float g_c1[HID];         // b2 @ Wl[4:36]
__device__ float g_c2[HID];         // b2 @ Wl[40:72]

// ---------------------------------------------------------------------------
// Kernel 0: padded-CSR rank build (deterministic) + weight folding.
// ---------------------------------------------------------------------------
__global__ void setup_kernel(const int* __restrict__ esrc,
                             const int* __restrict__ edst,
                             const float* __restrict__ W2,
                             const float* __restrict__ Wl,
                             const float* __restrict__ b2) {
    __shared__ int cnt[NN];
    __shared__ int offs[NN + 1];
    __shared__ int cnt2[NN];
    int t = threadIdx.x;            // blockDim = 1024
    if (t < NN) { cnt[t] = 0; cnt2[t] = 0; }
    __syncthreads();
    atomicAdd(&cnt[esrc[t]], 1);
    __syncthreads();
    if (t == 0) {
        int acc = 0;
        for (int n = 0; n < NN; n++) { offs[n] = acc; acc += (cnt[n] + 3) & ~3; }
        offs[NN] = acc;
    }
    __syncthreads();
    if (t < 32) {
        for (int c = 0; c < NE / 32; c++) {
            int e = c * 32 + t;
            int s = esrc[e];
            unsigned m = __match_any_sync(0xffffffffu, s);
            int within = __popc(m & ((1u << t) - 1u));
            int base = cnt2[s];
            __syncwarp();
            g_rank[e] = offs[s] + base + within;
            if (within == 0) cnt2[s] = base + __popc(m);
            __syncwarp();
        }
    }
    if (t <= NN) g_off[t] = offs[t];
    if (t < NN)  g_deg[t] = cnt[t];

    // fold W2 through Wl, transposed: M1t[k, j] = sum_i W2[j,i]*Wl[4+i,k]
    int j = t >> 5, k = t & 31;
    float a1 = 0.f, a2 = 0.f;
    for (int i = 0; i < 32; i++) {
        float w2 = W2[j * 32 + i];
        a1 = fmaf(w2, Wl[(4  + i) * 32 + k], a1);
        a2 = fmaf(w2, Wl[(40 + i) * 32 + k], a2);
    }
    g_M1t[k * MT + j] = a1;
    g_M2t[k * MT + j] = a2;
    if (t < 32) {
        float c1 = 0.f, c2 = 0.f;
        for (int i = 0; i < 32; i++) {
            c1 = fmaf(b2[i], Wl[(4  + i) * 32 + t], c1);
            c2 = fmaf(b2[i], Wl[(40 + i) * 32 + t], c2);
        }
        g_c1[t] = c1;
        g_c2[t] = c2;
    }
}

// ---------------------------------------------------------------------------
// Kernel 1: one block per graph. 73.6 KB smem -> 3 blocks/SM.
// ---------------------------------------------------------------------------
#define SMEM_WORDS 18392
#define SMEM_BYTES (SMEM_WORDS * 4)

__global__ __launch_bounds__(T, 3) void critic_kernel(
    const float* __restrict__ x,         // [B*64, 4]
    const float* __restrict__ edge_attr, // [B*1024, 2]
    const float* __restrict__ action,    // [B, 1027]
    const int*   __restrict__ edst,      // [1024]
    const float* __restrict__ W1,        // [10,32]
    const float* __restrict__ b1,        // [32]
    const float* __restrict__ Wl,        // [73,32]
    const float* __restrict__ bl,        // [32]
    const float* __restrict__ Wv,        // [32]
    const float* __restrict__ bv,        // [1]
    float* __restrict__ out)             // [B]
{
    extern __shared__ float sm[];
    float* W1s   = sm;          // 320
    float* b1s   = sm + 320;    // 32
    float* Xl1   = sm + 352;    // 128 (Wl rows 0..3)
    float* Xl2   = sm + 480;    // 128 (Wl rows 36..39)
    float* wl72s = sm + 608;    // 32
    float* bls   = sm + 640;    // 32
    float* Wvs   = sm + 672;    // 32
    float* c1s   = sm + 704;    // 32
    float* c2s   = sm + 736;    // 32
    float* M1ts  = sm + 768;    // 1152
    float* M2ts  = sm + 1920;   // 1152
    float* p1s   = sm + 3072;   // 2048
    float* p2s   = sm + 5120;   // 2080 (65 rows; row 64 = -1e30 sentinel)
    float* Hs    = sm + 7200;   // 2048
    float* g1s   = sm + 9248;   // 2048
    float* g2s   = sm + 11296;  // 2080 (65 rows; row 64 = -1e30 sentinel)
    float* ecf   = sm + 13376;  // 4864 (float4[1216]: ea0, ea1, dst<<7, act)
    float* facta = sm + 18240;  // 4
    float* wsum  = sm + 18244;  // 16
    int*   offs  = (int*)(sm + 18260); // 68
    int*   degs  = (int*)(sm + 18328); // 64
    float4* ecomb = (float4*)ecf;

    const int b   = blockIdx.x;
    const int tid = threadIdx.x;
    const int w   = tid >> 5;
    const int k   = tid & 31;
    const int e   = k >> 3;        // edge slot within quad
    const int q   = k & 7;         // channel group (channels 4q..4q+3)
    const int q4  = q << 2;

    // ---- phase A: weights, constants, sentinel rows, dummy ecomb fill ----
    for (int i = tid; i < 320; i += T) W1s[i] = W1[i];
    if (tid < 128) { Xl1[tid] = Wl[tid]; Xl2[tid] = Wl[36 * 32 + tid]; }
    if (tid < 32) {
        b1s[tid]   = b1[tid];
        wl72s[tid] = Wl[72 * 32 + tid];
        bls[tid]   = bl[tid];
        Wvs[tid]   = Wv[tid];
        c1s[tid]   = g_c1[tid];
        c2s[tid]   = g_c2[tid];
        p2s[64 * 32 + tid] = -1e30f;     // sentinel rows
        g2s[64 * 32 + tid] = -1e30f;
    }
    for (int i = tid; i < HID * MT; i += T) { M1ts[i] = g_M1t[i]; M2ts[i] = g_M2t[i]; }
    {
        float4 dmy = make_float4(0.f, 0.f, __int_as_float(64 << 7), 0.f);
        for (int i = tid; i < PADE; i += T) ecomb[i] = dmy;
    }
    if (tid < NF) facta[tid] = action[b * NROWS + NE + tid];
    if (tid <= NN) offs[tid] = g_off[tid];
    if (tid < NN)  degs[tid] = g_deg[tid];
    __syncthreads();

    // ---- phase B: scatter real edges + per-node precomputes ----
    for (int i = tid; i < NE; i += T) {
        int   rk = g_rank[i];                               // coalesced
        float2 v = ((const float2*)edge_attr)[b * NE + i];  // coalesced
        float  a = action[b * NROWS + i];                   // coalesced
        int    d = edst[i];                                 // coalesced
        ecomb[rk] = make_float4(v.x, v.y, __int_as_float(d << 7), a);
    }
    {
        const float4* xg = (const float4*)(x + (size_t)b * 256);
        for (int i = tid; i < NN * HID; i += T) {
            int n = i >> 5, j = i & 31;
            float4 xv = __ldg(&xg[n]);                      // L1 broadcast
            p1s[i] = fmaf(xv.x, W1s[j],       fmaf(xv.y, W1s[32 + j],
                     fmaf(xv.z, W1s[64 + j],  fmaf(xv.w, W1s[96 + j], b1s[j]))));
            p2s[i] = fmaf(xv.x, W1s[128 + j], fmaf(xv.y, W1s[160 + j],
                     fmaf(xv.z, W1s[192 + j], xv.w * W1s[224 + j])));
            g1s[i] = fmaf(xv.x, Xl1[j],       fmaf(xv.y, Xl1[32 + j],
                     fmaf(xv.z, Xl1[64 + j],  fmaf(xv.w, Xl1[96 + j], bls[j]))));
            g2s[i] = fmaf(xv.x, Xl2[j],       fmaf(xv.y, Xl2[32 + j],
                     fmaf(xv.z, Xl2[64 + j],  xv.w * Xl2[96 + j])));
        }
    }
    __syncthreads();

    // ---- H[n,k] = sum_{edges of n} relu(p1[n]+p2[dst]+ea@W1[8:10]) ----
    // lane = 8e+q: edge slot e of each quad, channels 4q..4q+3 (2 packed pairs)
    {
        const char* p2q = (const char*)p2s + (q << 4);
        u64 w8a = pk2(W1s[256 + q4],     W1s[256 + q4 + 1]);
        u64 w8b = pk2(W1s[256 + q4 + 2], W1s[256 + q4 + 3]);
        u64 w9a = pk2(W1s[288 + q4],     W1s[288 + q4 + 1]);
        u64 w9b = pk2(W1s[288 + q4 + 2], W1s[288 + q4 + 3]);
        #pragma unroll
        for (int nn = 0; nn < 4; nn++) {
            int n = w * 4 + nn;
            int beg = offs[n], end = offs[n + 1];   // padded: (end-beg)%4==0
            u64 p1a = dll(*(const double*)(p1s + n * 32 + q4));
            u64 p1b = dll(*(const double*)(p1s + n * 32 + q4 + 2));
            u64 a01 = 0ull, a23 = 0ull;
            #pragma unroll 2
            for (int i0 = beg + e; i0 < end; i0 += 4) {
                float4 ec = ecomb[i0];                      // 64B -> ~1 wf
                int dofs = __float_as_int(ec.z);            // dst*128 bytes
                double2 pv = *(const double2*)(p2q + dofs); // LDS.128 gather
                u64 ex = dup2(ec.x), ey = dup2(ec.y);
                u64 s01 = f2add(p1a, dll(pv.x));
                u64 s23 = f2add(p1b, dll(pv.y));
                s01 = f2fma(ex, w8a, s01); s01 = f2fma(ey, w9a, s01);
                s23 = f2fma(ex, w8b, s23); s23 = f2fma(ey, w9b, s23);
                a01 = f2add(a01, relu2(s01));
                a23 = f2add(a23, relu2(s23));
            }
            float2 f01 = up2(a01), f23 = up2(a23);
            f01.x += __shfl_xor_sync(0xffffffffu, f01.x, 8);
            f01.y += __shfl_xor_sync(0xffffffffu, f01.y, 8);
            f23.x += __shfl_xor_sync(0xffffffffu, f23.x, 8);
            f23.y += __shfl_xor_sync(0xffffffffu, f23.y, 8);
            f01.x += __shfl_xor_sync(0xffffffffu, f01.x, 16);
            f01.y += __shfl_xor_sync(0xffffffffu, f01.y, 16);
            f23.x += __shfl_xor_sync(0xffffffffu, f23.x, 16);
            f23.y += __shfl_xor_sync(0xffffffffu, f23.y, 16);
            if (e == 0)
                *(float4*)(Hs + n * 32 + q4) = make_float4(f01.x, f01.y, f23.x, f23.y);
        }
    }
    __syncthreads();

    // ---- g{1,2}[n,k] += H[n]@M{1,2} + deg*c{1,2}; warps 0-7: g1, 8-15: g2 ----
    {
        int hf = w >> 3, wl_ = w & 7;
        const float* Mts = hf ? M2ts : M1ts;
        float*       gsd = hf ? g2s : g1s;
        float ck = hf ? c2s[k] : c1s[k];
        u64 Mreg[16];
        const double2* mp = (const double2*)(Mts + k * MT);
        #pragma unroll
        for (int jj = 0; jj < 8; jj++) {
            double2 mv = mp[jj];                             // 8 LDS.128
            Mreg[2 * jj]     = dll(mv.x);
            Mreg[2 * jj + 1] = dll(mv.y);
        }
        #pragma unroll
        for (int nn = 0; nn < 8; nn++) {
            int n = wl_ * 8 + nn;
            u64 acc2 = 0ull;
            const double2* hp = (const double2*)(Hs + n * 32);
            #pragma unroll
            for (int jj = 0; jj < 8; jj++) {
                double2 hv = hp[jj];                         // LDS.128 broadcast
                acc2 = f2fma(dll(hv.x), Mreg[2 * jj],     acc2);
                acc2 = f2fma(dll(hv.y), Mreg[2 * jj + 1], acc2);
            }
            float2 af = up2(acc2);
            gsd[n * 32 + k] = gsd[n * 32 + k] + af.x + af.y
                              + (float)degs[n] * ck;
        }
    }
    __syncthreads();

    // ---- rows (padded CSR): v = relu(g1[src]+g2[dst]+act*wl72) @ Wv ----
    {
        const char* g2q = (const char*)g2s + (q << 4);
        u64 wlA = pk2(wl72s[q4],     wl72s[q4 + 1]);
        u64 wlB = pk2(wl72s[q4 + 2], wl72s[q4 + 3]);
        u64 wvA = pk2(Wvs[q4],       Wvs[q4 + 1]);
        u64 wvB = pk2(Wvs[q4 + 2],   Wvs[q4 + 3]);
        u64 v01 = 0ull, v23 = 0ull;
        #pragma unroll
        for (int nn = 0; nn < 4; nn++) {
            int n = w * 4 + nn;
            int beg = offs[n], end = offs[n + 1];
            u64 g1a = dll(*(const double*)(g1s + n * 32 + q4));
            u64 g1b = dll(*(const double*)(g1s + n * 32 + q4 + 2));
            #pragma unroll 2
            for (int i0 = beg + e; i0 < end; i0 += 4) {
                float4 ec = ecomb[i0];
                int dofs = __float_as_int(ec.z);
                double2 gv = *(const double2*)(g2q + dofs);  // LDS.128 gather
                u64 aw = dup2(ec.w);
                u64 s01 = f2add(f2fma(aw, wlA, g1a), dll(gv.x));
                u64 s23 = f2add(f2fma(aw, wlB, g1b), dll(gv.y));
                v01 = f2fma(relu2(s01), wvA, v01);
                v23 = f2fma(relu2(s23), wvB, v23);
            }
        }
        if (w < NF && e == 0) {                    // factory rows
            int n = NN - NF + w;
            u64 g1a = dll(*(const double*)(g1s + n * 32 + q4));
            u64 g1b = dll(*(const double*)(g1s + n * 32 + q4 + 2));
            double2 gv = *(const double2*)((const char*)g2s + (n << 7) + (q << 4));
            u64 aw = dup2(facta[w]);
            u64 s01 = f2add(f2fma(aw, wlA, g1a), dll(gv.x));
            u64 s23 = f2add(f2fma(aw, wlB, g1b), dll(gv.y));
            v01 = f2fma(relu2(s01), wvA, v01);
            v23 = f2fma(relu2(s23), wvB, v23);
        }
        float2 va = up2(v01), vb = up2(v23);
        float vacc = (va.x + va.y) + (vb.x + vb.y);
        #pragma unroll
        for (int o = 16; o > 0; o >>= 1)
            vacc += __shfl_xor_sync(0xffffffffu, vacc, o);
        if (k == 0) wsum[w] = vacc;
    }
    __syncthreads();
    if (tid == 0) {
        float tot = 0.f;
        #pragma unroll
        for (int i = 0; i < 16; i++) tot += wsum[i];
        out[b] = tot + (float)NROWS * bv[0];
    }
}

// ---------------------------------------------------------------------------
extern "C" void kernel_launch(void* const* d_in, const int* in_sizes, int n_in,
                              void* d_out, int out_size) {
    const float* x         = (const float*)d_in[0];
    // d_in[1] = edge_index: redundant, unused
    const float* edge_attr = (const float*)d_in[2];
    const float* action    = (const float*)d_in[3];
    const int*   esrc      = (const int*)d_in[4];
    const int*   edst      = (const int*)d_in[5];
    const float* W1        = (const float*)d_in[6];
    const float* b1        = (const float*)d_in[7];
    const float* W2        = (const float*)d_in[8];
    const float* b2        = (const float*)d_in[9];
    const float* Wl        = (const float*)d_in[10];
    const float* bl        = (const float*)d_in[11];
    const float* Wv        = (const float*)d_in[12];
    const float* bv        = (const float*)d_in[13];
    float* out = (float*)d_out;

    cudaFuncSetAttribute(critic_kernel,
                         cudaFuncAttributeMaxDynamicSharedMemorySize,
                         SMEM_BYTES);

    setup_kernel<<<1, 1024>>>(esrc, edst, W2, Wl, b2);
    critic_kernel<<<out_size, T, SMEM_BYTES>>>(
        x, edge_attr, action, edst, W1, b1, Wl, bl, Wv, bv, out);
}

// round 7
// speedup vs baseline: 1.0043x; 1.0043x over previous
#include <cuda_runtime.h>

#define NN    64          // nodes per graph
#define HID   32
#define NE    1024        // edges per graph
#define NF    3
#define NROWS (NE + NF)   // 1027
#define T     512
#define MT    36          // padded transposed-M row stride
#define PADE  1216        // max padded CSR length

typedef unsigned long long u64;

__device__ __forceinline__ u64 pk2(float x, float y) {
    u64 r; asm("mov.b64 %0,{%1,%2};" : "=l"(r) : "f"(x), "f"(y)); return r;
}
__device__ __forceinline__ float2 up2(u64 a) {
    float2 r; asm("mov.b64 {%0,%1},%2;" : "=f"(r.x), "=f"(r.y) : "l"(a)); return r;
}
__device__ __forceinline__ u64 f2fma(u64 a, u64 b, u64 c) {
    u64 r; asm("fma.rn.f32x2 %0,%1,%2,%3;" : "=l"(r) : "l"(a), "l"(b), "l"(c)); return r;
}
__device__ __forceinline__ u64 dll(double d) { return __double_as_longlong(d); }

// batch-invariant scratch
__device__ int   g_off[NN + 1];     // padded CSR offsets (each segment %4==0)
__device__ int   g_deg[NN];         // true degrees
__device__ int   g_rank[NE];        // padded CSR slot of original edge e
__device__ float g_M1t[HID * MT];   // (W2 @ Wl[4:36])^T, padded stride 36
__device__ float g_M2t[HID * MT];   // (W2 @ Wl[40:72])^T
__device__ float g_c1[HID];         // b2 @ Wl[4:36]
__device__ float g_c2[HID];         // b2 @ Wl[40:72]

// ---------------------------------------------------------------------------
// Kernel 0: padded-CSR rank build (deterministic) + weight folding.
// ---------------------------------------------------------------------------
__global__ void setup_kernel(const int* __restrict__ esrc,
                             const int* __restrict__ edst,
                             const float* __restrict__ W2,
                             const float* __restrict__ Wl,
                             const float* __restrict__ b2) {
    __shared__ int cnt[NN];
    __shared__ int offs[NN + 1];
    __shared__ int cnt2[NN];
    int t = threadIdx.x;            // blockDim = 1024
    if (t < NN) { cnt[t] = 0; cnt2[t] = 0; }
    __syncthreads();
    atomicAdd(&cnt[esrc[t]], 1);
    __syncthreads();
    if (t == 0) {
        int acc = 0;
        for (int n = 0; n < NN; n++) { offs[n] = acc; acc += (cnt[n] + 3) & ~3; }
        offs[NN] = acc;
    }
    __syncthreads();
    if (t < 32) {
        for (int c = 0; c < NE / 32; c++) {
            int e = c * 32 + t;
            int s = esrc[e];
            unsigned m = __match_any_sync(0xffffffffu, s);
            int within = __popc(m & ((1u << t) - 1u));
            int base = cnt2[s];
            __syncwarp();
            g_rank[e] = offs[s] + base + within;
            if (within == 0) cnt2[s] = base + __popc(m);
            __syncwarp();
        }
    }
    if (t <= NN) g_off[t] = offs[t];
    if (t < NN)  g_deg[t] = cnt[t];

    // fold W2 through Wl, transposed: M1t[k, j] = sum_i W2[j,i]*Wl[4+i,k]
    int j = t >> 5, k = t & 31;
    float a1 = 0.f, a2 = 0.f;
    for (int i = 0; i < 32; i++) {
        float w2 = W2[j * 32 + i];
        a1 = fmaf(w2, Wl[(4  + i) * 32 + k], a1);
        a2 = fmaf(w2, Wl[(40 + i) * 32 + k], a2);
    }
    g_M1t[k * MT + j] = a1;
    g_M2t[k * MT + j] = a2;
    if (t < 32) {
        float c1 = 0.f, c2 = 0.f;
        for (int i = 0; i < 32; i++) {
            c1 = fmaf(b2[i], Wl[(4  + i) * 32 + t], c1);
            c2 = fmaf(b2[i], Wl[(40 + i) * 32 + t], c2);
        }
        g_c1[t] = c1;
        g_c2[t] = c2;
    }
}

// ---------------------------------------------------------------------------
// Kernel 1: one block per graph. ~73.6 KB smem -> 3 blocks/SM.
// ---------------------------------------------------------------------------
#define SMEM_WORDS 18392
#define SMEM_BYTES (SMEM_WORDS * 4)

__global__ __launch_bounds__(T, 3) void critic_kernel(
    const float* __restrict__ x,         // [B*64, 4]
    const float* __restrict__ edge_attr, // [B*1024, 2]
    const float* __restrict__ action,    // [B, 1027]
    const int*   __restrict__ edst,      // [1024]
    const float* __restrict__ W1,        // [10,32]
    const float* __restrict__ b1,        // [32]
    const float* __restrict__ Wl,        // [73,32]
    const float* __restrict__ bl,        // [32]
    const float* __restrict__ Wv,        // [32]
    const float* __restrict__ bv,        // [1]
    float* __restrict__ out)             // [B]
{
    extern __shared__ float sm[];
    float* W1s   = sm;          // 320
    float* b1s   = sm + 320;    // 32
    float* Xl1   = sm + 352;    // 128 (Wl rows 0..3)
    float* Xl2   = sm + 480;    // 128 (Wl rows 36..39)
    float* wl72s = sm + 608;    // 32
    float* bls   = sm + 640;    // 32
    float* Wvs   = sm + 672;    // 32
    float* c1s   = sm + 704;    // 32
    float* c2s   = sm + 736;    // 32
    float* M1ts  = sm + 768;    // 1152
    float* M2ts  = sm + 1920;   // 1152
    float* p1s   = sm + 3072;   // 2048
    float* p2s   = sm + 5120;   // 2080 (65 rows; row 64 = -1e30 sentinel)
    float* Hs    = sm + 7200;   // 2048
    float* g1s   = sm + 9248;   // 2048
    float* g2s   = sm + 11296;  // 2080 (65 rows; row 64 = -1e30 sentinel)
    float* ecf   = sm + 13376;  // 4864 (float4[1216]: ea0, ea1, dst*32, act)
    float* facta = sm + 18240;  // 4
    float* wsum  = sm + 18244;  // 16
    int*   offs  = (int*)(sm + 18260); // 68
    int*   degs  = (int*)(sm + 18328); // 64
    float4* ecomb = (float4*)ecf;

    const int b   = blockIdx.x;
    const int tid = threadIdx.x;
    const int w   = tid >> 5;
    const int k   = tid & 31;
    const int e   = k >> 3;        // edge slot within quad
    const int q   = k & 7;         // channel group (channels 4q..4q+3)
    const int q4  = q << 2;

    // ---- phase A: weights, constants, sentinels, offsets ----
    for (int i = tid; i < 320; i += T) W1s[i] = W1[i];
    if (tid < 128) { Xl1[tid] = Wl[tid]; Xl2[tid] = Wl[36 * 32 + tid]; }
    if (tid < 32) {
        b1s[tid]   = b1[tid];
        wl72s[tid] = Wl[72 * 32 + tid];
        bls[tid]   = bl[tid];
        Wvs[tid]   = Wv[tid];
        c1s[tid]   = g_c1[tid];
        c2s[tid]   = g_c2[tid];
        p2s[64 * 32 + tid] = -1e30f;     // sentinel rows (relu kills dummies)
        g2s[64 * 32 + tid] = -1e30f;
    }
    for (int i = tid; i < HID * MT; i += T) { M1ts[i] = g_M1t[i]; M2ts[i] = g_M2t[i]; }
    if (tid < NF) facta[tid] = action[b * NROWS + NE + tid];
    if (tid <= NN) offs[tid] = g_off[tid];
    if (tid < NN)  degs[tid] = g_deg[tid];
    __syncthreads();

    // ---- phase B: dummy pad slots, real-edge scatter, per-node precomputes ----
    if (tid < NN) {                       // <=3 dummy slots per node
        float4 dmy = make_float4(0.f, 0.f, __int_as_float(64 << 5), 0.f);
        int st = offs[tid] + degs[tid], en = offs[tid + 1];
        for (int i = st; i < en; i++) ecomb[i] = dmy;
    }
    for (int i = tid; i < NE; i += T) {
        int   rk = g_rank[i];                               // coalesced
        float2 v = ((const float2*)edge_attr)[b * NE + i];  // coalesced
        float  a = action[b * NROWS + i];                   // coalesced
        int    d = edst[i];                                 // coalesced
        ecomb[rk] = make_float4(v.x, v.y, __int_as_float(d << 5), a);
    }
    {
        const float4* xg = (const float4*)(x + (size_t)b * 256);
        for (int i = tid; i < NN * HID; i += T) {
            int n = i >> 5, j = i & 31;
            float4 xv = __ldg(&xg[n]);                      // L1 broadcast
            p1s[i] = fmaf(xv.x, W1s[j],       fmaf(xv.y, W1s[32 + j],
                     fmaf(xv.z, W1s[64 + j],  fmaf(xv.w, W1s[96 + j], b1s[j]))));
            p2s[i] = fmaf(xv.x, W1s[128 + j], fmaf(xv.y, W1s[160 + j],
                     fmaf(xv.z, W1s[192 + j], xv.w * W1s[224 + j])));
            g1s[i] = fmaf(xv.x, Xl1[j],       fmaf(xv.y, Xl1[32 + j],
                     fmaf(xv.z, Xl1[64 + j],  fmaf(xv.w, Xl1[96 + j], bls[j]))));
            g2s[i] = fmaf(xv.x, Xl2[j],       fmaf(xv.y, Xl2[32 + j],
                     fmaf(xv.z, Xl2[64 + j],  xv.w * Xl2[96 + j])));
        }
    }
    __syncthreads();

    // ---- H[n,k] = sum_{edges of n} relu(p1[n]+p2[dst]+ea@W1[8:10]) ----
    // lane = 8e+q: edge slot e of each quad, channels 4q..4q+3 (float4, 4
    // independent FMA streams per lane; padded -> unpredicated)
    {
        float4 w8q = *(const float4*)(W1s + 256 + q4);
        float4 w9q = *(const float4*)(W1s + 288 + q4);
        #pragma unroll
        for (int nn = 0; nn < 4; nn++) {
            int n = w * 4 + nn;
            int beg = offs[n], end = offs[n + 1];
            float4 p1v = *(const float4*)(p1s + n * 32 + q4);
            float4 acc = make_float4(0.f, 0.f, 0.f, 0.f);
            #pragma unroll 2
            for (int i0 = beg + e; i0 < end; i0 += 4) {
                float4 ec = ecomb[i0];                       // 4x16B -> bcast
                int didx = __float_as_int(ec.z);             // dst*32
                float4 p2v = *(const float4*)(p2s + didx + q4);
                float4 pre;
                pre.x = fmaf(ec.x, w8q.x, fmaf(ec.y, w9q.x, p1v.x + p2v.x));
                pre.y = fmaf(ec.x, w8q.y, fmaf(ec.y, w9q.y, p1v.y + p2v.y));
                pre.z = fmaf(ec.x, w8q.z, fmaf(ec.y, w9q.z, p1v.z + p2v.z));
                pre.w = fmaf(ec.x, w8q.w, fmaf(ec.y, w9q.w, p1v.w + p2v.w));
                acc.x += fmaxf(pre.x, 0.f);
                acc.y += fmaxf(pre.y, 0.f);
                acc.z += fmaxf(pre.z, 0.f);
                acc.w += fmaxf(pre.w, 0.f);
            }
            acc.x += __shfl_xor_sync(0xffffffffu, acc.x, 8);
            acc.y += __shfl_xor_sync(0xffffffffu, acc.y, 8);
            acc.z += __shfl_xor_sync(0xffffffffu, acc.z, 8);
            acc.w += __shfl_xor_sync(0xffffffffu, acc.w, 8);
            acc.x += __shfl_xor_sync(0xffffffffu, acc.x, 16);
            acc.y += __shfl_xor_sync(0xffffffffu, acc.y, 16);
            acc.z += __shfl_xor_sync(0xffffffffu, acc.z, 16);
            acc.w += __shfl_xor_sync(0xffffffffu, acc.w, 16);
            if (e == 0)
                *(float4*)(Hs + n * 32 + q4) = acc;
        }
    }
    __syncthreads();

    // ---- g{1,2}[n,k] += H[n]@M{1,2} + deg*c{1,2}; warps 0-7: g1, 8-15: g2 ----
    // dense stage: f32x2 packed math, transposed-M register cache
    {
        int hf = w >> 3, wl_ = w & 7;
        const float* Mts = hf ? M2ts : M1ts;
        float*       gsd = hf ? g2s : g1s;
        float ck = hf ? c2s[k] : c1s[k];
        u64 Mreg[16];
        const double2* mp = (const double2*)(Mts + k * MT);
        #pragma unroll
        for (int jj = 0; jj < 8; jj++) {
            double2 mv = mp[jj];                             // 8 LDS.128
            Mreg[2 * jj]     = dll(mv.x);
            Mreg[2 * jj + 1] = dll(mv.y);
        }
        #pragma unroll
        for (int nn = 0; nn < 8; nn++) {
            int n = wl_ * 8 + nn;
            u64 acc2 = 0ull;
            const double2* hp = (const double2*)(Hs + n * 32);
            #pragma unroll
            for (int jj = 0; jj < 8; jj++) {
                double2 hv = hp[jj];                         // LDS.128 broadcast
                acc2 = f2fma(dll(hv.x), Mreg[2 * jj],     acc2);
                acc2 = f2fma(dll(hv.y), Mreg[2 * jj + 1], acc2);
            }
            float2 af = up2(acc2);
            gsd[n * 32 + k] = gsd[n * 32 + k] + af.x + af.y
                              + (float)degs[n] * ck;
        }
    }
    __syncthreads();

    // ---- rows (padded CSR): v = relu(g1[src]+g2[dst]+act*wl72) @ Wv ----
    {
        float4 wlq = *(const float4*)(wl72s + q4);
        float4 wvq = *(const float4*)(Wvs + q4);
        float4 va = make_float4(0.f, 0.f, 0.f, 0.f);
        #pragma unroll
        for (int nn = 0; nn < 4; nn++) {
            int n = w * 4 + nn;
            int beg = offs[n], end = offs[n + 1];
            float4 g1v = *(const float4*)(g1s + n * 32 + q4);
            #pragma unroll 2
            for (int i0 = beg + e; i0 < end; i0 += 4) {
                float4 ec = ecomb[i0];
                int didx = __float_as_int(ec.z);
                float4 g2v = *(const float4*)(g2s + didx + q4);
                float4 pre;
                pre.x = fmaf(ec.w, wlq.x, g1v.x) + g2v.x;
                pre.y = fmaf(ec.w, wlq.y, g1v.y) + g2v.y;
                pre.z = fmaf(ec.w, wlq.z, g1v.z) + g2v.z;
                pre.w = fmaf(ec.w, wlq.w, g1v.w) + g2v.w;
                va.x = fmaf(fmaxf(pre.x, 0.f), wvq.x, va.x);
                va.y = fmaf(fmaxf(pre.y, 0.f), wvq.y, va.y);
                va.z = fmaf(fmaxf(pre.z, 0.f), wvq.z, va.z);
                va.w = fmaf(fmaxf(pre.w, 0.f), wvq.w, va.w);
            }
        }
        if (w < NF && e == 0) {                    // factory rows
            int n = NN - NF + w;
            float fa = facta[w];
            float4 g1v = *(const float4*)(g1s + n * 32 + q4);
            float4 g2v = *(const float4*)(g2s + n * 32 + q4);
            float4 pre;
            pre.x = fmaf(fa, wlq.x, g1v.x) + g2v.x;
            pre.y = fmaf(fa, wlq.y, g1v.y) + g2v.y;
            pre.z = fmaf(fa, wlq.z, g1v.z) + g2v.z;
            pre.w = fmaf(fa, wlq.w, g1v.w) + g2v.w;
            va.x = fmaf(fmaxf(pre.x, 0.f), wvq.x, va.x);
            va.y = fmaf(fmaxf(pre.y, 0.f), wvq.y, va.y);
            va.z = fmaf(fmaxf(pre.z, 0.f), wvq.z, va.z);
            va.w = fmaf(fmaxf(pre.w, 0.f), wvq.w, va.w);
        }
        float vacc = (va.x + va.y) + (va.z + va.w);
        #pragma unroll
        for (int o = 16; o > 0; o >>= 1)
            vacc += __shfl_xor_sync(0xffffffffu, vacc, o);
        if (k == 0) wsum[w] = vacc;
    }
    __syncthreads();
    if (tid == 0) {
        float tot = 0.f;
        #pragma unroll
        for (int i = 0; i < 16; i++) tot += wsum[i];
        out[b] = tot + (float)NROWS * bv[0];
    }
}

// ---------------------------------------------------------------------------
extern "C" void kernel_launch(void* const* d_in, const int* in_sizes, int n_in,
                              void* d_out, int out_size) {
    const float* x         = (const float*)d_in[0];
    // d_in[1] = edge_index: redundant, unused
    const float* edge_attr = (const float*)d_in[2];
    const float* action    = (const float*)d_in[3];
    const int*   esrc      = (const int*)d_in[4];
    const int*   edst      = (const int*)d_in[5];
    const float* W1        = (const float*)d_in[6];
    const float* b1        = (const float*)d_in[7];
    const float* W2        = (const float*)d_in[8];
    const float* b2        = (const float*)d_in[9];
    const float* Wl        = (const float*)d_in[10];
    const float* bl        = (const float*)d_in[11];
    const float* Wv        = (const float*)d_in[12];
    const float* bv        = (const float*)d_in[13];
    float* out = (float*)d_out;

    cudaFuncSetAttribute(critic_kernel,
                         cudaFuncAttributeMaxDynamicSharedMemorySize,
                         SMEM_BYTES);

    setup_kernel<<<1, 1024>>>(esrc, edst, W2, Wl, b2);
    critic_kernel<<<out_size, T, SMEM_BYTES>>>(
        x, edge_attr, action, edst, W1, b1, Wl, bl, Wv, bv, out);
}